// round 12
// baseline (speedup 1.0000x reference)
#include <cuda_runtime.h>
#include <cuda_bf16.h>
#include <math.h>
#include <stdint.h>

#define Wn 2048
#define Cn 24
#define Vn 101
#define En 512
#define H1 1024
#define H2 1024
#define G1 3072
#define G2 3072
#define Kd 1024
#define KP 3072
#define NCTA2 128
#define STEPS 2048

// ---- scratch (__device__ globals; no allocations allowed) ----
__device__ float g_table[Vn * G1];
__device__ float g_h1[Wn * H1];
__device__ float g_gh[Wn * G1];
__device__ float g_gif[Wn * G2];
__device__ float g_gib[Wn * G2];
__device__ float g_h2[2][2][H2];        // [dir][parity][dim]
__device__ unsigned g_flag[2][64][32];  // per-CTA step flags, 128B padded
__device__ __nv_bfloat16 g_Ap[Wn * KP];        // [Ah | Ah | Al]
__device__ __nv_bfloat16 g_Wp1[G1 * KP];       // [Wh | Wl | Wh]
__device__ __nv_bfloat16 g_Wp2f[G2 * KP];
__device__ __nv_bfloat16 g_Wp2b[G2 * KP];

// =================== PTX helpers ===================
__device__ __forceinline__ uint32_t smem_u32(const void* p) {
    uint32_t a;
    asm("{ .reg .u64 t; cvta.to.shared.u64 t, %1; cvt.u32.u64 %0, t; }" : "=r"(a) : "l"(p));
    return a;
}
__device__ __forceinline__ void cpasync16(uint32_t dst, const void* src) {
    asm volatile("cp.async.cg.shared.global [%0], [%1], 16;" :: "r"(dst), "l"(src));
}
#define CP_COMMIT() asm volatile("cp.async.commit_group;" ::: "memory")
#define CP_WAIT1()  asm volatile("cp.async.wait_group 1;" ::: "memory")

__device__ __forceinline__ void ldm4(uint32_t* r, uint32_t addr) {
    asm volatile("ldmatrix.sync.aligned.m8n8.x4.shared.b16 {%0,%1,%2,%3}, [%4];"
        : "=r"(r[0]), "=r"(r[1]), "=r"(r[2]), "=r"(r[3]) : "r"(addr));
}
__device__ __forceinline__ void ldm2(uint32_t* r, uint32_t addr) {
    asm volatile("ldmatrix.sync.aligned.m8n8.x2.shared.b16 {%0,%1}, [%2];"
        : "=r"(r[0]), "=r"(r[1]) : "r"(addr));
}
__device__ __forceinline__ void mma16816(float* d, const uint32_t* a, const uint32_t* b) {
    asm volatile("mma.sync.aligned.m16n8k16.row.col.f32.bf16.bf16.f32 "
        "{%0,%1,%2,%3}, {%4,%5,%6,%7}, {%8,%9}, {%0,%1,%2,%3};"
        : "+f"(d[0]), "+f"(d[1]), "+f"(d[2]), "+f"(d[3])
        : "r"(a[0]), "r"(a[1]), "r"(a[2]), "r"(a[3]), "r"(b[0]), "r"(b[1]));
}
__device__ __forceinline__ void st_release(unsigned* p, unsigned v) {
    asm volatile("st.release.gpu.global.u32 [%0], %1;" :: "l"(p), "r"(v) : "memory");
}
__device__ __forceinline__ unsigned ld_acquire(const unsigned* p) {
    unsigned v;
    asm volatile("ld.acquire.gpu.global.u32 %0, [%1];" : "=r"(v) : "l"(p) : "memory");
    return v;
}
__device__ __forceinline__ float tanh_fast(float x) {
    float y;
    asm("tanh.approx.f32 %0, %1;" : "=f"(y) : "f"(x));
    return y;
}
__device__ __forceinline__ float sigmoid_fast(float x) {
    return fmaf(tanh_fast(0.5f * x), 0.5f, 0.5f);
}

// =================== bf16 HMMA GEMM: tile 128x96, k-step 64, 3-stage ===================
// grid (N/96, M/128) = (32,16) = 512 CTAs -> 86.5% wave efficiency at occ 2.
// 8 warps x (64x24). Row stride 144B; stage = 224 rows = 32,256 B.
#define STG 32256
#define AB_OFF 18432         // B rows start at 128*144
#define NKIT (KP / 64)       // 48

__global__ void __launch_bounds__(256, 2) gemm_mma(
    const __nv_bfloat16* __restrict__ Ap, const __nv_bfloat16* __restrict__ Bp,
    float* __restrict__ C, const float* __restrict__ bias, int N) {
    extern __shared__ __align__(16) char smem[];
    const uint32_t sb = smem_u32(smem);
    const int tid = threadIdx.x, lane = tid & 31, warp = tid >> 5;
    const int wm = warp & 1, wn = warp >> 1;
    const int bm = blockIdx.y * 128, bn = blockIdx.x * 96;

    // cp.async: 7 chunks/thread. id = tid + i*256; row = id>>3 (0..223), ch = id&7.
    uint32_t soff[7];
    const __nv_bfloat16* src[7];
#pragma unroll
    for (int i = 0; i < 7; i++) {
        int id = tid + i * 256;
        int row = id >> 3, ch = id & 7;
        soff[i] = (uint32_t)row * 144 + (uint32_t)ch * 16;
        src[i] = (row < 128 ? Ap + (size_t)(bm + row) * KP
                            : Bp + (size_t)(bn + row - 128) * KP) + ch * 8;
    }

    const uint32_t aPre = (uint32_t)(wm * 64 + ((lane >> 3) & 1) * 8 + (lane & 7)) * 144
                        + (uint32_t)(lane >> 4) * 16;
    const uint32_t bPre = (uint32_t)AB_OFF
                        + (uint32_t)(wn * 24 + (lane >> 4) * 8 + (lane & 7)) * 144
                        + (uint32_t)((lane >> 3) & 1) * 16;
    const uint32_t bPre2 = (uint32_t)AB_OFF
                        + (uint32_t)(wn * 24 + 16 + (lane & 7)) * 144
                        + (uint32_t)((lane >> 3) & 1) * 16;

    float acc[4][3][4];
#pragma unroll
    for (int i = 0; i < 4; i++)
#pragma unroll
        for (int j = 0; j < 3; j++)
#pragma unroll
            for (int q = 0; q < 4; q++) acc[i][j][q] = 0.f;

#define ISSUE(s, k0) do { \
    uint32_t base_ = sb + (s) * STG; \
    cpasync16(base_ + soff[0], src[0] + (k0)); \
    cpasync16(base_ + soff[1], src[1] + (k0)); \
    cpasync16(base_ + soff[2], src[2] + (k0)); \
    cpasync16(base_ + soff[3], src[3] + (k0)); \
    cpasync16(base_ + soff[4], src[4] + (k0)); \
    cpasync16(base_ + soff[5], src[5] + (k0)); \
    cpasync16(base_ + soff[6], src[6] + (k0)); \
} while (0)

    ISSUE(0, 0); CP_COMMIT();
    ISSUE(1, 64); CP_COMMIT();

    for (int it = 0; it < NKIT; it++) {
        CP_WAIT1();
        __syncthreads();
        if (it + 2 < NKIT) ISSUE((it + 2) % 3, (it + 2) * 64);
        CP_COMMIT();

        const uint32_t abase = sb + (it % 3) * STG;
#pragma unroll
        for (int ks = 0; ks < 4; ks++) {
            uint32_t a[4][4], b4[4], b2[2];
#pragma unroll
            for (int ma = 0; ma < 4; ma++) ldm4(a[ma], abase + aPre + ma * 2304 + ks * 32);
            ldm4(b4, abase + bPre + ks * 32);
            ldm2(b2, abase + bPre2 + ks * 32);
#pragma unroll
            for (int ma = 0; ma < 4; ma++) {
                mma16816(acc[ma][0], a[ma], &b4[0]);
                mma16816(acc[ma][1], a[ma], &b4[2]);
                mma16816(acc[ma][2], a[ma], b2);
            }
        }
    }
#undef ISSUE

    const int g = lane >> 2, t = lane & 3;
#pragma unroll
    for (int ma = 0; ma < 4; ma++) {
        int m0 = bm + wm * 64 + ma * 16 + g;
#pragma unroll
        for (int nb = 0; nb < 3; nb++) {
            int col = bn + wn * 24 + nb * 8 + t * 2;
            float b0 = bias[col], b1 = bias[col + 1];
            *(float2*)(C + (size_t)m0 * N + col) =
                make_float2(acc[ma][nb][0] + b0, acc[ma][nb][1] + b1);
            *(float2*)(C + (size_t)(m0 + 8) * N + col) =
                make_float2(acc[ma][nb][2] + b0, acc[ma][nb][3] + b1);
        }
    }
}

// =================== conversions (also per-replay init) ===================
__global__ void convsplit_kernel(const float* __restrict__ w,
                                 __nv_bfloat16* __restrict__ wp) {
    int i = blockIdx.x * 256 + threadIdx.x;
    if (i < 4 * H2) ((float*)g_h2)[i] = 0.f;
    if (i < 2 * 64 * 32) ((unsigned*)g_flag)[i] = 0u;
    if (i >= G1 * Kd) return;
    int r = i >> 10, k = i & 1023;
    float v = w[i];
    __nv_bfloat16 h = __float2bfloat16(v);
    __nv_bfloat16 l = __float2bfloat16(v - __bfloat162float(h));
    __nv_bfloat16* row = wp + (size_t)r * KP;
    row[k] = h; row[Kd + k] = l; row[2 * Kd + k] = h;
}

__global__ void table_kernel(const float* __restrict__ emb,
                             const float* __restrict__ Wih1,
                             const float* __restrict__ bih1) {
    __shared__ __align__(16) float e[En];
    int v = blockIdx.y;
    int tid = threadIdx.x, warp = tid >> 5, lane = tid & 31;
    for (int i = tid; i < En; i += 256) e[i] = emb[v * En + i];
    __syncthreads();
    int rbase = blockIdx.x * 64 + warp * 8;
    for (int rr = 0; rr < 8; rr++) {
        int row = rbase + rr;
        const float4* wp = (const float4*)(Wih1 + (size_t)row * En);
        const float4* ep = (const float4*)e;
        float s = 0.f;
#pragma unroll
        for (int k = 0; k < 4; k++) {
            float4 wv = wp[lane + 32 * k];
            float4 ev = ep[lane + 32 * k];
            s += wv.x * ev.x + wv.y * ev.y + wv.z * ev.z + wv.w * ev.w;
        }
        for (int off = 16; off; off >>= 1) s += __shfl_xor_sync(0xffffffffu, s, off);
        if (lane == 0) g_table[v * G1 + row] = s + bih1[row];
    }
}

// ---- layer-1 GRU pointwise: one block per word, 4 dims/thread ----
__global__ void gru1_kernel(const int* __restrict__ x, float* __restrict__ out,
                            int t, const float* __restrict__ bhh) {
    const int w = blockIdx.x, tid = threadIdx.x, j = tid * 4;
    const int ch = x[w * Cn + t];
    const float* tb = g_table + ch * G1;
    float4 ir = *(const float4*)(tb + j);
    float4 iz = *(const float4*)(tb + H1 + j);
    float4 in4 = *(const float4*)(tb + 2 * H1 + j);
    float4 hr, hz, hg, hp;
    if (t == 0) {
        hr = *(const float4*)(bhh + j);
        hz = *(const float4*)(bhh + H1 + j);
        hg = *(const float4*)(bhh + 2 * H1 + j);
        hp = make_float4(0.f, 0.f, 0.f, 0.f);
    } else {
        const float* gh = g_gh + (size_t)w * G1;
        hr = *(const float4*)(gh + j);
        hz = *(const float4*)(gh + H1 + j);
        hg = *(const float4*)(gh + 2 * H1 + j);
        hp = *(const float4*)(g_h1 + (size_t)w * H1 + j);
    }
    float hn[4], hl[4];
    {
        const float irv[4] = {ir.x, ir.y, ir.z, ir.w};
        const float izv[4] = {iz.x, iz.y, iz.z, iz.w};
        const float inv[4] = {in4.x, in4.y, in4.z, in4.w};
        const float hrv[4] = {hr.x, hr.y, hr.z, hr.w};
        const float hzv[4] = {hz.x, hz.y, hz.z, hz.w};
        const float hgv[4] = {hg.x, hg.y, hg.z, hg.w};
        const float hpv[4] = {hp.x, hp.y, hp.z, hp.w};
#pragma unroll
        for (int q = 0; q < 4; q++) {
            float r = sigmoid_fast(irv[q] + hrv[q]);
            float z = sigmoid_fast(izv[q] + hzv[q]);
            float n = tanh_fast(inv[q] + r * hgv[q]);
            hn[q] = (1.f - z) * n + z * hpv[q];
        }
    }
    *(float4*)(g_h1 + (size_t)w * H1 + j) = make_float4(hn[0], hn[1], hn[2], hn[3]);
    union { __nv_bfloat162 h2[2]; uint2 u; } PH, PL;
    PH.h2[0] = __floats2bfloat162_rn(hn[0], hn[1]);
    PH.h2[1] = __floats2bfloat162_rn(hn[2], hn[3]);
#pragma unroll
    for (int q = 0; q < 4; q++) {
        __nv_bfloat16 hb = __float2bfloat16(hn[q]);
        hl[q] = hn[q] - __bfloat162float(hb);
    }
    PL.h2[0] = __floats2bfloat162_rn(hl[0], hl[1]);
    PL.h2[1] = __floats2bfloat162_rn(hl[2], hl[3]);
    __nv_bfloat16* arow = g_Ap + (size_t)w * KP;
    *(uint2*)(arow + j) = PH.u;
    *(uint2*)(arow + Kd + j) = PH.u;
    *(uint2*)(arow + 2 * Kd + j) = PL.u;
    if (t == Cn - 1) *(float4*)(out + (size_t)w * H1 + j) = make_float4(hn[0], hn[1], hn[2], hn[3]);
}

// ---- layer-2 persistent bi-GRU: distributed per-CTA flags ----
__global__ void __launch_bounds__(256, 1) layer2_kernel(
    const float* __restrict__ Whhf, const float* __restrict__ Whhb,
    const float* __restrict__ bhhf, const float* __restrict__ bhhb,
    float* __restrict__ ctx) {
    __shared__ __align__(16) float hs[1024];
    const int tid = threadIdx.x, warp = tid >> 5, lane = tid & 31;
    const int cta = blockIdx.x, dir = cta >> 6, j0 = (cta & 63) << 4;
    const float* Whh = dir ? Whhb : Whhf;
    const float* bhh = dir ? bhhb : bhhf;
    const float* GI  = dir ? g_gib : g_gif;
    const int d0 = j0 + 2 * warp;

    float4 wreg[6][8];
#pragma unroll
    for (int u = 0; u < 2; u++)
#pragma unroll
        for (int gg = 0; gg < 3; gg++) {
            const float4* wp = (const float4*)(Whh + (size_t)(gg * H2 + d0 + u) * H2);
#pragma unroll
            for (int c = 0; c < 8; c++) wreg[u * 3 + gg][c] = wp[c * 32 + lane];
        }
    float bg[6];
#pragma unroll
    for (int u = 0; u < 2; u++)
#pragma unroll
        for (int gg = 0; gg < 3; gg++) bg[u * 3 + gg] = bhh[gg * H2 + d0 + u];

    for (int t = 0; t < STEPS; t++) {
        const int wd = dir ? (STEPS - 1 - t) : t;
        const float* gi = GI + (size_t)wd * G2;

        ((float4*)hs)[tid] = __ldcg(((const float4*)g_h2[dir][t & 1]) + tid);
        float giv[6];
        if (lane == 0) {
#pragma unroll
            for (int u = 0; u < 2; u++)
#pragma unroll
                for (int gg = 0; gg < 3; gg++) giv[u * 3 + gg] = gi[gg * H2 + d0 + u];
        }
        __syncthreads();

        float acc[6] = {0.f, 0.f, 0.f, 0.f, 0.f, 0.f};
#pragma unroll
        for (int c = 0; c < 8; c++) {
            float4 h4 = ((const float4*)hs)[c * 32 + lane];
#pragma unroll
            for (int rr = 0; rr < 6; rr++)
                acc[rr] += wreg[rr][c].x * h4.x + wreg[rr][c].y * h4.y
                         + wreg[rr][c].z * h4.z + wreg[rr][c].w * h4.w;
        }
#pragma unroll
        for (int off = 16; off; off >>= 1)
#pragma unroll
            for (int rr = 0; rr < 6; rr++)
                acc[rr] += __shfl_xor_sync(0xffffffffu, acc[rr], off);

        if (lane == 0) {
            float hnew[2];
#pragma unroll
            for (int u = 0; u < 2; u++) {
                float r = sigmoid_fast(giv[u * 3 + 0] + acc[u * 3 + 0] + bg[u * 3 + 0]);
                float z = sigmoid_fast(giv[u * 3 + 1] + acc[u * 3 + 1] + bg[u * 3 + 1]);
                float n = tanh_fast(giv[u * 3 + 2] + r * (acc[u * 3 + 2] + bg[u * 3 + 2]));
                hnew[u] = (1.f - z) * n + z * hs[d0 + u];
            }
            *(float2*)(ctx + (size_t)wd * (2 * H2) + dir * H2 + d0) = make_float2(hnew[0], hnew[1]);
            __stcg((float2*)&g_h2[dir][(t + 1) & 1][d0], make_float2(hnew[0], hnew[1]));
        }
        __syncthreads();

        // distributed flags: one release-store per CTA, 64 parallel pollers
        if (tid == 0) st_release(&g_flag[dir][cta & 63][0], (unsigned)(t + 1));
        if (tid < 64) {
            while (ld_acquire(&g_flag[dir][tid][0]) < (unsigned)(t + 1)) { __nanosleep(16); }
        }
        __syncthreads();
    }
}

extern "C" void kernel_launch(void* const* d_in, const int* in_sizes, int n_in,
                              void* d_out, int out_size) {
    const int*   x     = (const int*)d_in[0];
    const float* emb   = (const float*)d_in[1];
    const float* Wih1  = (const float*)d_in[2];
    const float* Whh1  = (const float*)d_in[3];
    const float* bih1  = (const float*)d_in[4];
    const float* bhh1  = (const float*)d_in[5];
    const float* Wih2f = (const float*)d_in[6];
    const float* Whh2f = (const float*)d_in[7];
    const float* bih2f = (const float*)d_in[8];
    const float* bhh2f = (const float*)d_in[9];
    const float* Wih2b = (const float*)d_in[10];
    const float* Whh2b = (const float*)d_in[11];
    const float* bih2b = (const float*)d_in[12];
    const float* bhh2b = (const float*)d_in[13];
    float* out = (float*)d_out;
    float* ctx = out + (size_t)Wn * H1;

    float *p_gh, *p_gif, *p_gib;
    cudaGetSymbolAddress((void**)&p_gh,  g_gh);
    cudaGetSymbolAddress((void**)&p_gif, g_gif);
    cudaGetSymbolAddress((void**)&p_gib, g_gib);
    __nv_bfloat16 *pAp, *pW1, *pW2f, *pW2b;
    cudaGetSymbolAddress((void**)&pAp,  g_Ap);
    cudaGetSymbolAddress((void**)&pW1,  g_Wp1);
    cudaGetSymbolAddress((void**)&pW2f, g_Wp2f);
    cudaGetSymbolAddress((void**)&pW2b, g_Wp2b);

    const int gsmem = 3 * STG;   // 96,768 B
    cudaFuncSetAttribute(gemm_mma, cudaFuncAttributeMaxDynamicSharedMemorySize, gsmem);
    dim3 gg(G1 / 96, Wn / 128);  // (32, 16) = 512 CTAs

    convsplit_kernel<<<(G1 * Kd + 255) / 256, 256>>>(Whh1, pW1);   // 0 (+init)
    table_kernel<<<dim3(G1 / 64, Vn), 256>>>(emb, Wih1, bih1);     // 1
    gru1_kernel<<<Wn, 256>>>(x, out, 0, bhh1);                     // 2
    for (int t = 1; t < Cn; t++) {
        gemm_mma<<<gg, 256, gsmem>>>(pAp, pW1, p_gh, bhh1, G1);    // 3, 5, ...
        gru1_kernel<<<Wn, 256>>>(x, out, t, bhh1);                 // 4, 6, ...
    }

    convsplit_kernel<<<(G2 * Kd + 255) / 256, 256>>>(Wih2f, pW2f);
    gemm_mma<<<gg, 256, gsmem>>>(pAp, pW2f, p_gif, bih2f, G2);
    convsplit_kernel<<<(G2 * Kd + 255) / 256, 256>>>(Wih2b, pW2b);
    gemm_mma<<<gg, 256, gsmem>>>(pAp, pW2b, p_gib, bih2b, G2);

    layer2_kernel<<<NCTA2, 256>>>(Whh2f, Whh2b, bhh2f, bhh2b, ctx);
}

// round 13
// speedup vs baseline: 1.0401x; 1.0401x over previous
#include <cuda_runtime.h>
#include <cuda_bf16.h>
#include <math.h>
#include <stdint.h>

#define Wn 2048
#define Cn 24
#define Vn 101
#define En 512
#define H1 1024
#define H2 1024
#define G1 3072
#define G2 3072
#define Kd 1024
#define KP 3072
#define NCTA2 128
#define STEPS 2048

// ---- scratch (__device__ globals; no allocations allowed) ----
__device__ float g_table[Vn * G1];
__device__ float g_h1[Wn * H1];
__device__ float g_gh[Wn * G1];
__device__ float g_gi2[Wn * 2 * G2];    // [word][fwd 3072 | bwd 3072]
__device__ float g_b2[2 * G2];          // [bih2f | bih2b]
__device__ float g_h2[2][2][H2];        // [dir][parity][dim]
__device__ unsigned g_bar2[2];
__device__ __nv_bfloat16 g_Ap[Wn * KP];          // [Ah | Ah | Al]
__device__ __nv_bfloat16 g_Wp1[G1 * KP];         // [Wh | Wl | Wh]
__device__ __nv_bfloat16 g_Wp2[2 * G2 * KP];     // [W2f' ; W2b']

// =================== PTX helpers ===================
__device__ __forceinline__ uint32_t smem_u32(const void* p) {
    uint32_t a;
    asm("{ .reg .u64 t; cvta.to.shared.u64 t, %1; cvt.u32.u64 %0, t; }" : "=r"(a) : "l"(p));
    return a;
}
__device__ __forceinline__ void cpasync16(uint32_t dst, const void* src) {
    asm volatile("cp.async.cg.shared.global [%0], [%1], 16;" :: "r"(dst), "l"(src));
}
#define CP_COMMIT() asm volatile("cp.async.commit_group;" ::: "memory")
#define CP_WAIT1()  asm volatile("cp.async.wait_group 1;" ::: "memory")

__device__ __forceinline__ void ldm4(uint32_t* r, uint32_t addr) {
    asm volatile("ldmatrix.sync.aligned.m8n8.x4.shared.b16 {%0,%1,%2,%3}, [%4];"
        : "=r"(r[0]), "=r"(r[1]), "=r"(r[2]), "=r"(r[3]) : "r"(addr));
}
__device__ __forceinline__ void mma16816(float* d, const uint32_t* a, const uint32_t* b) {
    asm volatile("mma.sync.aligned.m16n8k16.row.col.f32.bf16.bf16.f32 "
        "{%0,%1,%2,%3}, {%4,%5,%6,%7}, {%8,%9}, {%0,%1,%2,%3};"
        : "+f"(d[0]), "+f"(d[1]), "+f"(d[2]), "+f"(d[3])
        : "r"(a[0]), "r"(a[1]), "r"(a[2]), "r"(a[3]), "r"(b[0]), "r"(b[1]));
}
__device__ __forceinline__ void bar_arrive_release(unsigned* p) {
    asm volatile("red.release.gpu.global.add.u32 [%0], 1;" :: "l"(p) : "memory");
}
__device__ __forceinline__ unsigned ld_acquire(const unsigned* p) {
    unsigned v;
    asm volatile("ld.acquire.gpu.global.u32 %0, [%1];" : "=r"(v) : "l"(p) : "memory");
    return v;
}
__device__ __forceinline__ float tanh_fast(float x) {
    float y;
    asm("tanh.approx.f32 %0, %1;" : "=f"(y) : "f"(x));
    return y;
}
__device__ __forceinline__ float sigmoid_fast(float x) {
    return fmaf(tanh_fast(0.5f * x), 0.5f, 0.5f);
}

// =================== bf16 HMMA GEMM: k-step 64, 3-stage (R11-proven) ===================
#define STG 36864            // As 128*144 + Bs 128*144
#define HSTG 18432
#define NKIT (KP / 64)       // 48

__global__ void __launch_bounds__(256, 2) gemm_mma(
    const __nv_bfloat16* __restrict__ Ap, const __nv_bfloat16* __restrict__ Bp,
    float* __restrict__ C, const float* __restrict__ bias, int N) {
    extern __shared__ __align__(16) char smem[];
    const uint32_t sb = smem_u32(smem);
    const int tid = threadIdx.x, lane = tid & 31, warp = tid >> 5;
    const int wm = warp & 1, wn = warp >> 1;
    const int bm = blockIdx.y * 128, bn = blockIdx.x * 128;

    const int r1 = tid >> 2, c1 = tid & 3;
    const uint32_t oA = (uint32_t)r1 * 144 + (uint32_t)c1 * 16;
    const __nv_bfloat16* pa1 = Ap + (size_t)(bm + r1) * KP + c1 * 8;
    const __nv_bfloat16* pa2 = pa1 + (size_t)64 * KP;
    const __nv_bfloat16* pb1 = Bp + (size_t)(bn + r1) * KP + c1 * 8;
    const __nv_bfloat16* pb2 = pb1 + (size_t)64 * KP;

    const uint32_t aPre = (uint32_t)(wm * 64 + ((lane >> 3) & 1) * 8 + (lane & 7)) * 144
                        + (uint32_t)(lane >> 4) * 16;
    const uint32_t bPre = (uint32_t)(wn * 32 + (lane >> 4) * 8 + (lane & 7)) * 144
                        + (uint32_t)((lane >> 3) & 1) * 16;

    float acc[4][4][4];
#pragma unroll
    for (int i = 0; i < 4; i++)
#pragma unroll
        for (int j = 0; j < 4; j++)
#pragma unroll
            for (int q = 0; q < 4; q++) acc[i][j][q] = 0.f;

#define ISSUE(s, k0) do { \
    uint32_t as_ = sb + (s) * STG, bs_ = as_ + HSTG; \
    cpasync16(as_ + oA,              pa1 + (k0)); \
    cpasync16(as_ + oA + 64,         pa1 + (k0) + 32); \
    cpasync16(as_ + oA + 9216,       pa2 + (k0)); \
    cpasync16(as_ + oA + 9216 + 64,  pa2 + (k0) + 32); \
    cpasync16(bs_ + oA,              pb1 + (k0)); \
    cpasync16(bs_ + oA + 64,         pb1 + (k0) + 32); \
    cpasync16(bs_ + oA + 9216,       pb2 + (k0)); \
    cpasync16(bs_ + oA + 9216 + 64,  pb2 + (k0) + 32); \
} while (0)

    ISSUE(0, 0); CP_COMMIT();
    ISSUE(1, 64); CP_COMMIT();

    for (int it = 0; it < NKIT; it++) {
        CP_WAIT1();
        __syncthreads();
        if (it + 2 < NKIT) ISSUE((it + 2) % 3, (it + 2) * 64);
        CP_COMMIT();

        const uint32_t abase = sb + (it % 3) * STG;
        const uint32_t bbase = abase + HSTG;
#pragma unroll
        for (int ks = 0; ks < 4; ks++) {
            uint32_t a[4][4], bb[2][4];
#pragma unroll
            for (int ma = 0; ma < 4; ma++) ldm4(a[ma], abase + aPre + ma * 2304 + ks * 32);
#pragma unroll
            for (int nb = 0; nb < 2; nb++) ldm4(bb[nb], bbase + bPre + nb * 2304 + ks * 32);
#pragma unroll
            for (int ma = 0; ma < 4; ma++)
#pragma unroll
                for (int na = 0; na < 4; na++)
                    mma16816(acc[ma][na], a[ma], &bb[na >> 1][(na & 1) * 2]);
        }
    }
#undef ISSUE

    const int g = lane >> 2, t = lane & 3;
#pragma unroll
    for (int ma = 0; ma < 4; ma++) {
        int m0 = bm + wm * 64 + ma * 16 + g;
#pragma unroll
        for (int na = 0; na < 4; na++) {
            int col = bn + wn * 32 + na * 8 + t * 2;
            float b0 = bias[col], b1 = bias[col + 1];
            *(float2*)(C + (size_t)m0 * N + col) =
                make_float2(acc[ma][na][0] + b0, acc[ma][na][1] + b1);
            *(float2*)(C + (size_t)(m0 + 8) * N + col) =
                make_float2(acc[ma][na][2] + b0, acc[ma][na][3] + b1);
        }
    }
}

// =================== conversions (+ per-replay init, + bias copy) ===================
__global__ void convsplit_kernel(const float* __restrict__ w,
                                 __nv_bfloat16* __restrict__ wp,
                                 const float* __restrict__ bsrc,
                                 float* __restrict__ bdst) {
    int i = blockIdx.x * 256 + threadIdx.x;
    if (i < 4 * H2) ((float*)g_h2)[i] = 0.f;     // idempotent per-replay init
    if (i < 2) g_bar2[i] = 0u;
    if (bdst && i < G2 * 3) bdst[i] = bsrc[i];
    if (i >= G1 * Kd) return;
    int r = i >> 10, k = i & 1023;
    float v = w[i];
    __nv_bfloat16 h = __float2bfloat16(v);
    __nv_bfloat16 l = __float2bfloat16(v - __bfloat162float(h));
    __nv_bfloat16* row = wp + (size_t)r * KP;
    row[k] = h; row[Kd + k] = l; row[2 * Kd + k] = h;
}

__global__ void table_kernel(const float* __restrict__ emb,
                             const float* __restrict__ Wih1,
                             const float* __restrict__ bih1) {
    __shared__ __align__(16) float e[En];
    int v = blockIdx.y;
    int tid = threadIdx.x, warp = tid >> 5, lane = tid & 31;
    for (int i = tid; i < En; i += 256) e[i] = emb[v * En + i];
    __syncthreads();
    int rbase = blockIdx.x * 64 + warp * 8;
    for (int rr = 0; rr < 8; rr++) {
        int row = rbase + rr;
        const float4* wp = (const float4*)(Wih1 + (size_t)row * En);
        const float4* ep = (const float4*)e;
        float s = 0.f;
#pragma unroll
        for (int k = 0; k < 4; k++) {
            float4 wv = wp[lane + 32 * k];
            float4 ev = ep[lane + 32 * k];
            s += wv.x * ev.x + wv.y * ev.y + wv.z * ev.z + wv.w * ev.w;
        }
        for (int off = 16; off; off >>= 1) s += __shfl_xor_sync(0xffffffffu, s, off);
        if (lane == 0) g_table[v * G1 + row] = s + bih1[row];
    }
}

// ---- layer-1 GRU pointwise: one block per word, 4 dims/thread ----
__global__ void gru1_kernel(const int* __restrict__ x, float* __restrict__ out,
                            int t, const float* __restrict__ bhh) {
    const int w = blockIdx.x, tid = threadIdx.x, j = tid * 4;
    const int ch = x[w * Cn + t];
    const float* tb = g_table + ch * G1;
    float4 ir = *(const float4*)(tb + j);
    float4 iz = *(const float4*)(tb + H1 + j);
    float4 in4 = *(const float4*)(tb + 2 * H1 + j);
    float4 hr, hz, hg, hp;
    if (t == 0) {
        hr = *(const float4*)(bhh + j);
        hz = *(const float4*)(bhh + H1 + j);
        hg = *(const float4*)(bhh + 2 * H1 + j);
        hp = make_float4(0.f, 0.f, 0.f, 0.f);
    } else {
        const float* gh = g_gh + (size_t)w * G1;
        hr = *(const float4*)(gh + j);
        hz = *(const float4*)(gh + H1 + j);
        hg = *(const float4*)(gh + 2 * H1 + j);
        hp = *(const float4*)(g_h1 + (size_t)w * H1 + j);
    }
    float hn[4], hl[4];
    {
        const float irv[4] = {ir.x, ir.y, ir.z, ir.w};
        const float izv[4] = {iz.x, iz.y, iz.z, iz.w};
        const float inv[4] = {in4.x, in4.y, in4.z, in4.w};
        const float hrv[4] = {hr.x, hr.y, hr.z, hr.w};
        const float hzv[4] = {hz.x, hz.y, hz.z, hz.w};
        const float hgv[4] = {hg.x, hg.y, hg.z, hg.w};
        const float hpv[4] = {hp.x, hp.y, hp.z, hp.w};
#pragma unroll
        for (int q = 0; q < 4; q++) {
            float r = sigmoid_fast(irv[q] + hrv[q]);
            float z = sigmoid_fast(izv[q] + hzv[q]);
            float n = tanh_fast(inv[q] + r * hgv[q]);
            hn[q] = (1.f - z) * n + z * hpv[q];
        }
    }
    *(float4*)(g_h1 + (size_t)w * H1 + j) = make_float4(hn[0], hn[1], hn[2], hn[3]);
    union { __nv_bfloat162 h2[2]; uint2 u; } PH, PL;
    PH.h2[0] = __floats2bfloat162_rn(hn[0], hn[1]);
    PH.h2[1] = __floats2bfloat162_rn(hn[2], hn[3]);
#pragma unroll
    for (int q = 0; q < 4; q++) {
        __nv_bfloat16 hb = __float2bfloat16(hn[q]);
        hl[q] = hn[q] - __bfloat162float(hb);
    }
    PL.h2[0] = __floats2bfloat162_rn(hl[0], hl[1]);
    PL.h2[1] = __floats2bfloat162_rn(hl[2], hl[3]);
    __nv_bfloat16* arow = g_Ap + (size_t)w * KP;
    *(uint2*)(arow + j) = PH.u;
    *(uint2*)(arow + Kd + j) = PH.u;
    *(uint2*)(arow + 2 * Kd + j) = PL.u;
    if (t == Cn - 1) *(float4*)(out + (size_t)w * H1 + j) = make_float4(hn[0], hn[1], hn[2], hn[3]);
}

// ---- layer-2 persistent bi-GRU: R11-proven central barrier, hot poll ----
__global__ void __launch_bounds__(256, 1) layer2_kernel(
    const float* __restrict__ Whhf, const float* __restrict__ Whhb,
    const float* __restrict__ bhhf, const float* __restrict__ bhhb,
    float* __restrict__ ctx) {
    __shared__ __align__(16) float hs[1024];
    const int tid = threadIdx.x, warp = tid >> 5, lane = tid & 31;
    const int cta = blockIdx.x, dir = cta >> 6, j0 = (cta & 63) << 4;
    const float* Whh = dir ? Whhb : Whhf;
    const float* bhh = dir ? bhhb : bhhf;
    const float* GI  = g_gi2 + dir * G2;      // combined gi buffer, row stride 2*G2
    unsigned* barp = &g_bar2[dir];
    const int d0 = j0 + 2 * warp;

    float4 wreg[6][8];
#pragma unroll
    for (int u = 0; u < 2; u++)
#pragma unroll
        for (int gg = 0; gg < 3; gg++) {
            const float4* wp = (const float4*)(Whh + (size_t)(gg * H2 + d0 + u) * H2);
#pragma unroll
            for (int c = 0; c < 8; c++) wreg[u * 3 + gg][c] = wp[c * 32 + lane];
        }
    float bg[6];
#pragma unroll
    for (int u = 0; u < 2; u++)
#pragma unroll
        for (int gg = 0; gg < 3; gg++) bg[u * 3 + gg] = bhh[gg * H2 + d0 + u];

    for (int t = 0; t < STEPS; t++) {
        const int wd = dir ? (STEPS - 1 - t) : t;
        const float* gi = GI + (size_t)wd * (2 * G2);

        ((float4*)hs)[tid] = __ldcg(((const float4*)g_h2[dir][t & 1]) + tid);
        float giv[6];
        if (lane == 0) {
#pragma unroll
            for (int u = 0; u < 2; u++)
#pragma unroll
                for (int gg = 0; gg < 3; gg++) giv[u * 3 + gg] = gi[gg * H2 + d0 + u];
        }
        __syncthreads();

        float acc[6] = {0.f, 0.f, 0.f, 0.f, 0.f, 0.f};
#pragma unroll
        for (int c = 0; c < 8; c++) {
            float4 h4 = ((const float4*)hs)[c * 32 + lane];
#pragma unroll
            for (int rr = 0; rr < 6; rr++)
                acc[rr] += wreg[rr][c].x * h4.x + wreg[rr][c].y * h4.y
                         + wreg[rr][c].z * h4.z + wreg[rr][c].w * h4.w;
        }
#pragma unroll
        for (int off = 16; off; off >>= 1)
#pragma unroll
            for (int rr = 0; rr < 6; rr++)
                acc[rr] += __shfl_xor_sync(0xffffffffu, acc[rr], off);

        if (lane == 0) {
            float hnew[2];
#pragma unroll
            for (int u = 0; u < 2; u++) {
                float r = sigmoid_fast(giv[u * 3 + 0] + acc[u * 3 + 0] + bg[u * 3 + 0]);
                float z = sigmoid_fast(giv[u * 3 + 1] + acc[u * 3 + 1] + bg[u * 3 + 1]);
                float n = tanh_fast(giv[u * 3 + 2] + r * (acc[u * 3 + 2] + bg[u * 3 + 2]));
                hnew[u] = (1.f - z) * n + z * hs[d0 + u];
            }
            *(float2*)(ctx + (size_t)wd * (2 * H2) + dir * H2 + d0) = make_float2(hnew[0], hnew[1]);
            __stcg((float2*)&g_h2[dir][(t + 1) & 1][d0], make_float2(hnew[0], hnew[1]));
        }
        __syncthreads();

        if (tid == 0) {
            bar_arrive_release(barp);
            unsigned target = 64u * (unsigned)(t + 1);
            while (ld_acquire(barp) < target) { }   // hot poll: 64 pollers/dir, one line
        }
        __syncthreads();
    }
}

extern "C" void kernel_launch(void* const* d_in, const int* in_sizes, int n_in,
                              void* d_out, int out_size) {
    const int*   x     = (const int*)d_in[0];
    const float* emb   = (const float*)d_in[1];
    const float* Wih1  = (const float*)d_in[2];
    const float* Whh1  = (const float*)d_in[3];
    const float* bih1  = (const float*)d_in[4];
    const float* bhh1  = (const float*)d_in[5];
    const float* Wih2f = (const float*)d_in[6];
    const float* Whh2f = (const float*)d_in[7];
    const float* bih2f = (const float*)d_in[8];
    const float* bhh2f = (const float*)d_in[9];
    const float* Wih2b = (const float*)d_in[10];
    const float* Whh2b = (const float*)d_in[11];
    const float* bih2b = (const float*)d_in[12];
    const float* bhh2b = (const float*)d_in[13];
    float* out = (float*)d_out;
    float* ctx = out + (size_t)Wn * H1;

    float *p_gh, *p_gi2, *p_b2;
    cudaGetSymbolAddress((void**)&p_gh,  g_gh);
    cudaGetSymbolAddress((void**)&p_gi2, g_gi2);
    cudaGetSymbolAddress((void**)&p_b2,  g_b2);
    __nv_bfloat16 *pAp, *pW1, *pW2;
    cudaGetSymbolAddress((void**)&pAp, g_Ap);
    cudaGetSymbolAddress((void**)&pW1, g_Wp1);
    cudaGetSymbolAddress((void**)&pW2, g_Wp2);

    const int gsmem = 3 * STG;   // 110,592 B
    cudaFuncSetAttribute(gemm_mma, cudaFuncAttributeMaxDynamicSharedMemorySize, gsmem);
    dim3 gg(G1 / 128, Wn / 128);        // (24, 16)
    dim3 gg2(2 * G2 / 128, Wn / 128);   // (48, 16) combined tail gemm

    convsplit_kernel<<<(G1 * Kd + 255) / 256, 256>>>(Whh1, pW1, nullptr, nullptr);  // 0 (+init)
    table_kernel<<<dim3(G1 / 64, Vn), 256>>>(emb, Wih1, bih1);                      // 1
    gru1_kernel<<<Wn, 256>>>(x, out, 0, bhh1);                                      // 2
    for (int t = 1; t < Cn; t++) {
        gemm_mma<<<gg, 256, gsmem>>>(pAp, pW1, p_gh, bhh1, G1);                     // 3, 5, ...
        gru1_kernel<<<Wn, 256>>>(x, out, t, bhh1);                                  // 4, 6, ...
    }

    convsplit_kernel<<<(G2 * Kd + 255) / 256, 256>>>(Wih2f, pW2, bih2f, p_b2);
    convsplit_kernel<<<(G2 * Kd + 255) / 256, 256>>>(Wih2b, pW2 + (size_t)G2 * KP, bih2b, p_b2 + G2);
    gemm_mma<<<gg2, 256, gsmem>>>(pAp, pW2, p_gi2, p_b2, 2 * G2);

    layer2_kernel<<<NCTA2, 256>>>(Whh2f, Whh2b, bhh2f, bhh2b, ctx);
}